// round 15
// baseline (speedup 1.0000x reference)
#include <cuda_runtime.h>
#include <cuda_fp16.h>
#include <cstdint>
#include <math.h>

// Problem constants (fixed by the reference)
#define N_NODES 100000
#define E_EDGES 3200000
#define DD 256           // feature dim

// ---------------- scratch (static device allocations; no cudaMalloc) -------
__device__ int    g_is64;
__device__ int    g_cnt [N_NODES];
__device__ int    g_off [N_NODES + 1];
__device__ int    g_cur [N_NODES];
__device__ int2   g_ew  [E_EDGES];                // {src, bits(dis[src])} per CSR slot
__device__ float  g_dis [N_NODES];
__device__ __half g_x16 [N_NODES * DD];           // input features, fp16
__device__ __half g_xw1 [N_NODES * DD];           // layer-1 GEMM output
__device__ __half g_xw2 [N_NODES * DD];           // layer-2 GEMM output
__device__ __half g_h16 [N_NODES * DD];           // layer-1 activations, fp16
__device__ __half g_w1t [DD * DD];                // W1^T fp16 [n][k]
__device__ __half g_w2t [DD * DD];                // W2^T fp16 [n][k]

// ---------------------------------------------------------------------------
__global__ void k_detect(const int* __restrict__ ei32) {
    __shared__ int nz[256];
    int tid = threadIdx.x;
    int acc = 0;
    for (int i = tid; i < 2048; i += 256)
        acc += (ei32[2 * i + 1] != 0) ? 1 : 0;
    nz[tid] = acc;
    __syncthreads();
    for (int s = 128; s > 0; s >>= 1) {
        if (tid < s) nz[tid] += nz[tid + s];
        __syncthreads();
    }
    if (tid == 0) g_is64 = (nz[0] == 0) ? 1 : 0;
}

__global__ void k_zero_cnt() {
    int i = blockIdx.x * blockDim.x + threadIdx.x;
    if (i < N_NODES) g_cnt[i] = 0;
}

// histogram pass: decode dst on the fly
__global__ void k_count(const int* __restrict__ ei32) {
    int e = blockIdx.x * blockDim.x + threadIdx.x;
    if (e >= E_EDGES) return;
    int t = g_is64 ? ei32[2 * (E_EDGES + e)] : ei32[E_EDGES + e];
    atomicAdd(&g_cnt[t], 1);
}

__global__ __launch_bounds__(1024)
void k_scan() {
    __shared__ int sums[1024];
    const int tid = threadIdx.x;
    const int CH  = (N_NODES + 1023) / 1024;
    int beg = tid * CH;
    int end = beg + CH; if (end > N_NODES) end = N_NODES;
    if (beg > N_NODES) beg = N_NODES;

    int s = 0;
    for (int i = beg; i < end; i++) s += g_cnt[i];
    sums[tid] = s;
    __syncthreads();
    for (int off = 1; off < 1024; off <<= 1) {
        int v = (tid >= off) ? sums[tid - off] : 0;
        __syncthreads();
        sums[tid] += v;
        __syncthreads();
    }
    int run = (tid > 0) ? sums[tid - 1] : 0;
    for (int i = beg; i < end; i++) {
        int c = g_cnt[i];
        g_off[i] = run;
        g_cur[i] = run;
        g_dis[i] = rsqrtf((float)(c + 1));
        run += c;
    }
    if (tid == 0) g_off[N_NODES] = sums[1023];
}

// fill CSR slots with packed {src, dis[src]}; decode edges on the fly
__global__ void k_fill(const int* __restrict__ ei32) {
    int e = blockIdx.x * blockDim.x + threadIdx.x;
    if (e >= E_EDGES) return;
    int s, t;
    if (g_is64) {
        s = ei32[2 * e];
        t = ei32[2 * (E_EDGES + e)];
    } else {
        s = ei32[e];
        t = ei32[E_EDGES + e];
    }
    int p = atomicAdd(&g_cur[t], 1);
    g_ew[p] = make_int2(s, __float_as_int(g_dis[s]));
}

// ---------------------------------------------------------------------------
// x (fp32) -> fp16 copy
__global__ void k_cvt_x(const float* __restrict__ x) {
    int idx = blockIdx.x * blockDim.x + threadIdx.x;
    if (idx >= N_NODES * DD / 8) return;
    float4 a = *(const float4*)(x + idx * 8);
    float4 b = *(const float4*)(x + idx * 8 + 4);
    __half2 p0 = __floats2half2_rn(a.x, a.y);
    __half2 p1 = __floats2half2_rn(a.z, a.w);
    __half2 p2 = __floats2half2_rn(b.x, b.y);
    __half2 p3 = __floats2half2_rn(b.z, b.w);
    uint4 v = make_uint4(*(uint32_t*)&p0, *(uint32_t*)&p1,
                         *(uint32_t*)&p2, *(uint32_t*)&p3);
    *(uint4*)(g_x16 + idx * 8) = v;
}

// W^T -> fp16:  wt[n][k] = fp16(W[k][n])
__global__ void k_wcvt(const float* __restrict__ W, __half* __restrict__ wt) {
    int idx = blockIdx.x * blockDim.x + threadIdx.x;
    int n = idx >> 8, k = idx & 255;
    wt[n * DD + k] = __float2half_rn(W[k * DD + n]);
}

// ---------------------------------------------------------------------------
// mma.sync wrapper: m16n8k16 fp16 -> f32
__device__ __forceinline__ void mma_f16(float* c, const uint32_t* a, const uint32_t* b) {
    asm volatile(
        "mma.sync.aligned.m16n8k16.row.col.f32.f16.f16.f32 "
        "{%0,%1,%2,%3}, {%4,%5,%6,%7}, {%8,%9}, {%0,%1,%2,%3};"
        : "+f"(c[0]), "+f"(c[1]), "+f"(c[2]), "+f"(c[3])
        : "r"(a[0]), "r"(a[1]), "r"(a[2]), "r"(a[3]), "r"(b[0]), "r"(b[1]));
}

__device__ __forceinline__ void ldsm4(uint32_t* r, uint32_t saddr) {
    asm volatile("ldmatrix.sync.aligned.m8n8.x4.shared.b16 {%0,%1,%2,%3}, [%4];"
                 : "=r"(r[0]), "=r"(r[1]), "=r"(r[2]), "=r"(r[3]) : "r"(saddr));
}

__device__ __forceinline__ void cp16(uint32_t saddr, const void* g) {
    asm volatile("cp.async.cg.shared.global [%0], [%1], 16;"
                 :: "r"(saddr), "l"(g) : "memory");
}
#define CP_COMMIT() asm volatile("cp.async.commit_group;" ::: "memory")
#define CP_WAIT0()  asm volatile("cp.async.wait_group 0;" ::: "memory")
#define CP_WAIT1()  asm volatile("cp.async.wait_group 1;" ::: "memory")

// fp16 GEMM via mma.sync + ldmatrix, cp.async double-buffered, BK=64.
#define SA 72
#define STG (128 * SA)               // halfs per array per stage
__global__ __launch_bounds__(256, 2)
void k_gemm_mma(const __half* __restrict__ A, __half* __restrict__ C,
                const __half* __restrict__ Wt, int row_base, int M) {
    extern __shared__ __half sm[];   // [2][2][STG]: Af, Bf per stage

    const int tid  = threadIdx.x;
    const int wid  = tid >> 5;
    const int lane = tid & 31;
    const int wm   = wid & 3;
    const int wn   = wid >> 2;
    const int row0 = row_base + blockIdx.y * 128;
    const int bn   = blockIdx.x * 128;

    float acc[2][8][4];
#pragma unroll
    for (int i = 0; i < 2; i++)
#pragma unroll
        for (int j = 0; j < 8; j++)
#pragma unroll
            for (int q = 0; q < 4; q++) acc[i][j][q] = 0.0f;

    uint32_t sbase = (uint32_t)__cvta_generic_to_shared(sm);

    const int a_r = lane & 15;
    const int a_k = (lane >> 4) << 3;
    const int b_r = ((lane >> 4) << 3) + (lane & 7);
    const int b_k = ((lane >> 3) & 1) << 3;

    auto stage = [&](int p, int kb) {
        uint32_t bA = sbase + (uint32_t)(p * 2 * STG) * 2u;
        uint32_t bB = bA + (uint32_t)STG * 2u;
#pragma unroll
        for (int it = 0; it < 4; it++) {
            int idx = it * 256 + tid;     // 1024 uint4
            int r   = idx >> 3;           // 0..127
            int u   = idx & 7;            // 16B unit (8 per row)
            int gr  = row0 + r; if (gr >= M) gr = M - 1;
            cp16(bA + (uint32_t)(r * SA + u * 8) * 2u,
                 A + (size_t)gr * DD + kb + u * 8);
            cp16(bB + (uint32_t)(r * SA + u * 8) * 2u,
                 Wt + (size_t)(bn + r) * DD + kb + u * 8);
        }
        CP_COMMIT();
    };

    stage(0, 0);

    const int NK = DD / 64;              // 4 k-blocks
    for (int i = 0; i < NK; i++) {
        CP_WAIT0();
        __syncthreads();
        if (i + 1 < NK) stage((i + 1) & 1, (i + 1) * 64);

        uint32_t sAf = sbase + (uint32_t)((i & 1) * 2 * STG) * 2u;
        uint32_t sBf = sAf + (uint32_t)STG * 2u;

#pragma unroll
        for (int ks = 0; ks < 4; ks++) {
            const int k0 = ks * 16;
            uint32_t fb[8][2];
#pragma unroll
            for (int jp = 0; jp < 4; jp++) {
                int nj = wn * 64 + jp * 16;
                uint32_t addr = sBf + (uint32_t)((nj + b_r) * SA + k0 + b_k) * 2u;
                uint32_t r4[4];
                ldsm4(r4, addr);
                fb[jp * 2][0]     = r4[0];
                fb[jp * 2][1]     = r4[1];
                fb[jp * 2 + 1][0] = r4[2];
                fb[jp * 2 + 1][1] = r4[3];
            }
#pragma unroll
            for (int ii = 0; ii < 2; ii++) {
                int m0 = wm * 32 + ii * 16;
                uint32_t addr = sAf + (uint32_t)((m0 + a_r) * SA + k0 + a_k) * 2u;
                uint32_t fa[4];
                ldsm4(fa, addr);
#pragma unroll
                for (int j = 0; j < 8; j++)
                    mma_f16(acc[ii][j], fa, fb[j]);
            }
        }
    }

    // ---- epilogue: store fp16 ----
    const int lq = lane >> 2;
    const int lr = lane & 3;
#pragma unroll
    for (int i = 0; i < 2; i++) {
        int r_lo = row0 + wm * 32 + i * 16 + lq;
        int r_hi = r_lo + 8;
#pragma unroll
        for (int j = 0; j < 8; j++) {
            int col = bn + wn * 64 + j * 8 + lr * 2;
            if (r_lo < M) {
                __half2 p = __floats2half2_rn(acc[i][j][0], acc[i][j][1]);
                *(uint32_t*)(C + (size_t)r_lo * DD + col) = *(uint32_t*)&p;
            }
            if (r_hi < M) {
                __half2 p = __floats2half2_rn(acc[i][j][2], acc[i][j][3]);
                *(uint32_t*)(C + (size_t)r_hi * DD + col) = *(uint32_t*)&p;
            }
        }
    }
}
#define GEMM_SMEM (2 * 2 * STG * 2)   // bytes = 73728

// ---------------------------------------------------------------------------
// Fused aggregate + norm + bias + ELU via cp.async gather pipeline.
// 8 nodes per 256-thread block, one warp per node. Batches of 8 edge-rows
// (8 x 512B) staged into double-buffered smem; weight records stashed in smem.
#define AB       8                       // edges per batch
#define WBYTES   (AB * 512)              // data bytes per buffer  = 4096
#define EWOFF    (2 * WBYTES)            // ew area offset         = 8192
#define WARP_SM  (EWOFF + 2 * AB * 8)    // per-warp smem          = 8320
#define AGG_SMEM (8 * WARP_SM)           // per-block dynamic smem = 66560

template <bool OUT16>
__global__ __launch_bounds__(256)
void k_agg(const __half* __restrict__ xw16, const float* __restrict__ b,
           void* __restrict__ outp, int node_base, int node_cnt) {
    extern __shared__ char asmem[];
    const int warp = threadIdx.x >> 5;
    const int t    = threadIdx.x & 31;
    int node = node_base + blockIdx.x * 8 + warp;
    if (node >= node_base + node_cnt) return;

    char*    wbuf  = asmem + warp * WARP_SM;
    uint32_t wbase = (uint32_t)__cvta_generic_to_shared(wbuf);

    const uint4* X = (const uint4*)xw16;     // 32 uint4 per 512B row

    float dn = g_dis[node];
    float acc[8];
    {
        uint4 v = __ldg(&X[(size_t)node * 32 + t]);
        const __half2* h2 = (const __half2*)&v;
#pragma unroll
        for (int q = 0; q < 4; q++) {
            float2 f = __half22float2(h2[q]);
            acc[2 * q]     = dn * f.x;
            acc[2 * q + 1] = dn * f.y;
        }
    }

    const int beg = g_off[node];
    const int end = g_off[node + 1];
    const int deg = end - beg;
    const int nb  = (deg + AB - 1) / AB;

    // issue batch bi into buffer pb: cp.async 8 rows + stash ew in smem
    auto issue = [&](int bi, int pb) {
        int e0 = beg + bi * AB;
        int nv = end - e0; if (nv > AB) nv = AB;
        int2 ewl = make_int2(0, 0);
        if (t < nv) {
            ewl = __ldg(&g_ew[e0 + t]);
            *(int2*)(wbuf + EWOFF + pb * (AB * 8) + t * 8) = ewl;
        }
#pragma unroll
        for (int q = 0; q < AB; q++) {
            if (q < nv) {
                int src = __shfl_sync(0xffffffffu, ewl.x, q);
                cp16(wbase + (uint32_t)(pb * WBYTES + q * 512 + t * 16),
                     X + (size_t)src * 32 + t);
            }
        }
        CP_COMMIT();
    };

    // accumulate batch bi from buffer pb (cp.async for pb already waited)
    auto accum = [&](int bi, int pb) {
        __syncwarp();
        int e0 = beg + bi * AB;
        int nv = end - e0; if (nv > AB) nv = AB;
        const char* dat = wbuf + pb * WBYTES;
        const int2* ews = (const int2*)(wbuf + EWOFF + pb * (AB * 8));
#pragma unroll
        for (int q = 0; q < AB; q++) {
            if (q < nv) {
                float w = __int_as_float(ews[q].y);
                uint4 v = *(const uint4*)(dat + q * 512 + t * 16);
                const __half2* a = (const __half2*)&v;
#pragma unroll
                for (int p = 0; p < 4; p++) {
                    float2 f = __half22float2(a[p]);
                    acc[2 * p]     += w * f.x;
                    acc[2 * p + 1] += w * f.y;
                }
            }
        }
    };

    if (nb > 0) issue(0, 0);
    for (int bi = 0; bi < nb; bi++) {
        if (bi + 1 < nb) {
            issue(bi + 1, (bi + 1) & 1);
            CP_WAIT1();                  // batch bi complete, bi+1 in flight
        } else {
            CP_WAIT0();
        }
        accum(bi, bi & 1);
    }

    float4 b0 = *(const float4*)(b + t * 8);
    float4 b1 = *(const float4*)(b + t * 8 + 4);
    float r[8];
    r[0] = dn * acc[0] + b0.x;  r[1] = dn * acc[1] + b0.y;
    r[2] = dn * acc[2] + b0.z;  r[3] = dn * acc[3] + b0.w;
    r[4] = dn * acc[4] + b1.x;  r[5] = dn * acc[5] + b1.y;
    r[6] = dn * acc[6] + b1.z;  r[7] = dn * acc[7] + b1.w;
#pragma unroll
    for (int q = 0; q < 8; q++)
        r[q] = r[q] > 0.f ? r[q] : expm1f(r[q]);

    if (OUT16) {
        __half2 p0 = __floats2half2_rn(r[0], r[1]);
        __half2 p1 = __floats2half2_rn(r[2], r[3]);
        __half2 p2 = __floats2half2_rn(r[4], r[5]);
        __half2 p3 = __floats2half2_rn(r[6], r[7]);
        uint4 v = make_uint4(*(uint32_t*)&p0, *(uint32_t*)&p1,
                             *(uint32_t*)&p2, *(uint32_t*)&p3);
        *(uint4*)((__half*)outp + (size_t)node * DD + t * 8) = v;
    } else {
        float* O = (float*)outp + (size_t)node * DD + t * 8;
        __stcs((float4*)O,     make_float4(r[0], r[1], r[2], r[3]));
        __stcs((float4*)(O+4), make_float4(r[4], r[5], r[6], r[7]));
    }
}

// ---------------------------------------------------------------------------
extern "C" void kernel_launch(void* const* d_in, const int* in_sizes, int n_in,
                              void* d_out, int out_size) {
    const float* x   = (const float*)d_in[0];
    const int*   ei  = (const int*)d_in[1];
    const float* W1  = (const float*)d_in[2];
    const float* b1  = (const float*)d_in[3];
    const float* W2  = (const float*)d_in[4];
    const float* b2  = (const float*)d_in[5];
    float*       out = (float*)d_out;

    __half *x16, *xw1, *xw2, *h16, *w1t, *w2t;
    cudaGetSymbolAddress((void**)&x16, g_x16);
    cudaGetSymbolAddress((void**)&xw1, g_xw1);
    cudaGetSymbolAddress((void**)&xw2, g_xw2);
    cudaGetSymbolAddress((void**)&h16, g_h16);
    cudaGetSymbolAddress((void**)&w1t, g_w1t);
    cudaGetSymbolAddress((void**)&w2t, g_w2t);

    cudaFuncSetAttribute(k_gemm_mma,
                         cudaFuncAttributeMaxDynamicSharedMemorySize, GEMM_SMEM);
    cudaFuncSetAttribute(k_agg<true>,
                         cudaFuncAttributeMaxDynamicSharedMemorySize, AGG_SMEM);
    cudaFuncSetAttribute(k_agg<false>,
                         cudaFuncAttributeMaxDynamicSharedMemorySize, AGG_SMEM);

    const int T = 256;
    int grid_n   = (N_NODES + T - 1) / T;
    int grid_e   = (E_EDGES + T - 1) / T;
    int grid_cvt = (N_NODES * DD / 8 + T - 1) / T;

    // 2-chunk layer-boundary interleave: 100000 = 50048 + 49952
    const int CH0 = 50048;                  // multiple of 128
    int chunk_beg[2] = {0, CH0};
    int chunk_cnt[2] = {CH0, N_NODES - CH0};

    dim3 gemm_all(DD / 128, (N_NODES + 127) / 128);
    int agg_all = (N_NODES + 7) / 8;

    cudaStream_t s2;
    cudaStreamCreate(&s2);
    cudaEvent_t evFork, evW, evJoin, evA[2], evG[2];
    cudaEventCreateWithFlags(&evFork, cudaEventDisableTiming);
    cudaEventCreateWithFlags(&evW,    cudaEventDisableTiming);
    cudaEventCreateWithFlags(&evJoin, cudaEventDisableTiming);
    for (int i = 0; i < 2; i++) {
        cudaEventCreateWithFlags(&evA[i], cudaEventDisableTiming);
        cudaEventCreateWithFlags(&evG[i], cudaEventDisableTiming);
    }

    // fork side stream
    cudaEventRecord(evFork, 0);
    cudaStreamWaitEvent(s2, evFork, 0);

    // main: weight conversions first, then CSR build
    k_wcvt<<<DD, DD>>>(W1, w1t);
    k_wcvt<<<DD, DD>>>(W2, w2t);
    cudaEventRecord(evW, 0);

    // s2: x conversion, then layer-1 GEMM -> xw1
    k_cvt_x<<<grid_cvt, T, 0, s2>>>(x);
    cudaStreamWaitEvent(s2, evW, 0);
    k_gemm_mma<<<gemm_all, T, GEMM_SMEM, s2>>>(x16, xw1, w1t, 0, N_NODES);
    cudaEventRecord(evJoin, s2);

    // main: edge decode + CSR build + normalization (overlaps with s2)
    k_detect  <<<1, 256>>>(ei);
    k_zero_cnt<<<grid_n, T>>>();
    k_count   <<<grid_e, T>>>(ei);
    k_scan    <<<1, 1024>>>();
    k_fill    <<<grid_e, T>>>(ei);

    // join; layer-1 aggregation (reads xw1) in 2 chunks; GEMM-2 chunk
    // (reads h16 chunk, writes xw2 -- disjoint from xw1) trails on s2.
    cudaStreamWaitEvent(0, evJoin, 0);
    for (int i = 0; i < 2; i++) {
        k_agg<true><<<(chunk_cnt[i] + 7) / 8, T, AGG_SMEM>>>(
            xw1, b1, h16, chunk_beg[i], chunk_cnt[i]);
        cudaEventRecord(evA[i], 0);
        cudaStreamWaitEvent(s2, evA[i], 0);
        dim3 g2(DD / 128, (chunk_cnt[i] + 127) / 128);
        k_gemm_mma<<<g2, T, GEMM_SMEM, s2>>>(h16, xw2, w2t,
                                             chunk_beg[i], N_NODES);
        cudaEventRecord(evG[i], s2);
    }

    // main: wait for all GEMM-2 chunks, then full layer-2 aggregation
    for (int i = 0; i < 2; i++) cudaStreamWaitEvent(0, evG[i], 0);
    k_agg<false><<<agg_all, T, AGG_SMEM>>>(xw2, b2, out, 0, N_NODES);

    cudaStreamDestroy(s2);
    cudaEventDestroy(evFork);
    cudaEventDestroy(evW);
    cudaEventDestroy(evJoin);
    for (int i = 0; i < 2; i++) {
        cudaEventDestroy(evA[i]);
        cudaEventDestroy(evG[i]);
    }
}

// round 16
// speedup vs baseline: 1.0326x; 1.0326x over previous
#include <cuda_runtime.h>
#include <cuda_fp16.h>
#include <cstdint>
#include <math.h>

// Problem constants (fixed by the reference)
#define N_NODES 100000
#define E_EDGES 3200000
#define DD 256           // feature dim

// ---------------- scratch (static device allocations; no cudaMalloc) -------
__device__ int    g_is64;
__device__ int    g_tick[8];                      // work-steal counters
__device__ int    g_cnt [N_NODES];
__device__ int    g_off [N_NODES + 1];
__device__ int    g_cur [N_NODES];
__device__ int2   g_ew  [E_EDGES];                // {src, bits(dis[src])} per CSR slot
__device__ float  g_dis [N_NODES];
__device__ __half g_x16 [N_NODES * DD];           // input features, fp16
__device__ __half g_xw1 [N_NODES * DD];           // layer-1 GEMM output
__device__ __half g_xw2 [N_NODES * DD];           // layer-2 GEMM output
__device__ __half g_h16 [N_NODES * DD];           // layer-1 activations, fp16
__device__ __half g_w1t [DD * DD];                // W1^T fp16 [n][k]
__device__ __half g_w2t [DD * DD];                // W2^T fp16 [n][k]

// ---------------------------------------------------------------------------
__global__ void k_detect(const int* __restrict__ ei32) {
    __shared__ int nz[256];
    int tid = threadIdx.x;
    if (tid < 8) g_tick[tid] = 0;                 // reset work-steal counters
    int acc = 0;
    for (int i = tid; i < 2048; i += 256)
        acc += (ei32[2 * i + 1] != 0) ? 1 : 0;
    nz[tid] = acc;
    __syncthreads();
    for (int s = 128; s > 0; s >>= 1) {
        if (tid < s) nz[tid] += nz[tid + s];
        __syncthreads();
    }
    if (tid == 0) g_is64 = (nz[0] == 0) ? 1 : 0;
}

__global__ void k_zero_cnt() {
    int i = blockIdx.x * blockDim.x + threadIdx.x;
    if (i < N_NODES) g_cnt[i] = 0;
}

// histogram pass: decode dst on the fly
__global__ void k_count(const int* __restrict__ ei32) {
    int e = blockIdx.x * blockDim.x + threadIdx.x;
    if (e >= E_EDGES) return;
    int t = g_is64 ? ei32[2 * (E_EDGES + e)] : ei32[E_EDGES + e];
    atomicAdd(&g_cnt[t], 1);
}

__global__ __launch_bounds__(1024)
void k_scan() {
    __shared__ int sums[1024];
    const int tid = threadIdx.x;
    const int CH  = (N_NODES + 1023) / 1024;
    int beg = tid * CH;
    int end = beg + CH; if (end > N_NODES) end = N_NODES;
    if (beg > N_NODES) beg = N_NODES;

    int s = 0;
    for (int i = beg; i < end; i++) s += g_cnt[i];
    sums[tid] = s;
    __syncthreads();
    for (int off = 1; off < 1024; off <<= 1) {
        int v = (tid >= off) ? sums[tid - off] : 0;
        __syncthreads();
        sums[tid] += v;
        __syncthreads();
    }
    int run = (tid > 0) ? sums[tid - 1] : 0;
    for (int i = beg; i < end; i++) {
        int c = g_cnt[i];
        g_off[i] = run;
        g_cur[i] = run;
        g_dis[i] = rsqrtf((float)(c + 1));
        run += c;
    }
    if (tid == 0) g_off[N_NODES] = sums[1023];
}

// fill CSR slots with packed {src, dis[src]}; decode edges on the fly
__global__ void k_fill(const int* __restrict__ ei32) {
    int e = blockIdx.x * blockDim.x + threadIdx.x;
    if (e >= E_EDGES) return;
    int s, t;
    if (g_is64) {
        s = ei32[2 * e];
        t = ei32[2 * (E_EDGES + e)];
    } else {
        s = ei32[e];
        t = ei32[E_EDGES + e];
    }
    int p = atomicAdd(&g_cur[t], 1);
    g_ew[p] = make_int2(s, __float_as_int(g_dis[s]));
}

// ---------------------------------------------------------------------------
// x (fp32) -> fp16 copy
__global__ void k_cvt_x(const float* __restrict__ x) {
    int idx = blockIdx.x * blockDim.x + threadIdx.x;
    if (idx >= N_NODES * DD / 8) return;
    float4 a = *(const float4*)(x + idx * 8);
    float4 b = *(const float4*)(x + idx * 8 + 4);
    __half2 p0 = __floats2half2_rn(a.x, a.y);
    __half2 p1 = __floats2half2_rn(a.z, a.w);
    __half2 p2 = __floats2half2_rn(b.x, b.y);
    __half2 p3 = __floats2half2_rn(b.z, b.w);
    uint4 v = make_uint4(*(uint32_t*)&p0, *(uint32_t*)&p1,
                         *(uint32_t*)&p2, *(uint32_t*)&p3);
    *(uint4*)(g_x16 + idx * 8) = v;
}

// W^T -> fp16:  wt[n][k] = fp16(W[k][n])
__global__ void k_wcvt(const float* __restrict__ W, __half* __restrict__ wt) {
    int idx = blockIdx.x * blockDim.x + threadIdx.x;
    int n = idx >> 8, k = idx & 255;
    wt[n * DD + k] = __float2half_rn(W[k * DD + n]);
}

// ---------------------------------------------------------------------------
// mma.sync wrapper: m16n8k16 fp16 -> f32
__device__ __forceinline__ void mma_f16(float* c, const uint32_t* a, const uint32_t* b) {
    asm volatile(
        "mma.sync.aligned.m16n8k16.row.col.f32.f16.f16.f32 "
        "{%0,%1,%2,%3}, {%4,%5,%6,%7}, {%8,%9}, {%0,%1,%2,%3};"
        : "+f"(c[0]), "+f"(c[1]), "+f"(c[2]), "+f"(c[3])
        : "r"(a[0]), "r"(a[1]), "r"(a[2]), "r"(a[3]), "r"(b[0]), "r"(b[1]));
}

__device__ __forceinline__ void ldsm4(uint32_t* r, uint32_t saddr) {
    asm volatile("ldmatrix.sync.aligned.m8n8.x4.shared.b16 {%0,%1,%2,%3}, [%4];"
                 : "=r"(r[0]), "=r"(r[1]), "=r"(r[2]), "=r"(r[3]) : "r"(saddr));
}

__device__ __forceinline__ void cp16(uint32_t saddr, const void* g) {
    asm volatile("cp.async.cg.shared.global [%0], [%1], 16;"
                 :: "r"(saddr), "l"(g) : "memory");
}
#define CP_COMMIT() asm volatile("cp.async.commit_group;" ::: "memory")
#define CP_WAIT0()  asm volatile("cp.async.wait_group 0;" ::: "memory")

// fp16 GEMM via mma.sync + ldmatrix, cp.async double-buffered, BK=64.
#define SA 72
#define STG (128 * SA)               // halfs per array per stage
__global__ __launch_bounds__(256, 2)
void k_gemm_mma(const __half* __restrict__ A, __half* __restrict__ C,
                const __half* __restrict__ Wt, int row_base, int M) {
    extern __shared__ __half sm[];   // [2][2][STG]: Af, Bf per stage

    const int tid  = threadIdx.x;
    const int wid  = tid >> 5;
    const int lane = tid & 31;
    const int wm   = wid & 3;
    const int wn   = wid >> 2;
    const int row0 = row_base + blockIdx.y * 128;
    const int bn   = blockIdx.x * 128;

    float acc[2][8][4];
#pragma unroll
    for (int i = 0; i < 2; i++)
#pragma unroll
        for (int j = 0; j < 8; j++)
#pragma unroll
            for (int q = 0; q < 4; q++) acc[i][j][q] = 0.0f;

    uint32_t sbase = (uint32_t)__cvta_generic_to_shared(sm);

    const int a_r = lane & 15;
    const int a_k = (lane >> 4) << 3;
    const int b_r = ((lane >> 4) << 3) + (lane & 7);
    const int b_k = ((lane >> 3) & 1) << 3;

    auto stage = [&](int p, int kb) {
        uint32_t bA = sbase + (uint32_t)(p * 2 * STG) * 2u;
        uint32_t bB = bA + (uint32_t)STG * 2u;
#pragma unroll
        for (int it = 0; it < 4; it++) {
            int idx = it * 256 + tid;     // 1024 uint4
            int r   = idx >> 3;           // 0..127
            int u   = idx & 7;            // 16B unit (8 per row)
            int gr  = row0 + r; if (gr >= M) gr = M - 1;
            cp16(bA + (uint32_t)(r * SA + u * 8) * 2u,
                 A + (size_t)gr * DD + kb + u * 8);
            cp16(bB + (uint32_t)(r * SA + u * 8) * 2u,
                 Wt + (size_t)(bn + r) * DD + kb + u * 8);
        }
        CP_COMMIT();
    };

    stage(0, 0);

    const int NK = DD / 64;              // 4 k-blocks
    for (int i = 0; i < NK; i++) {
        CP_WAIT0();
        __syncthreads();
        if (i + 1 < NK) stage((i + 1) & 1, (i + 1) * 64);

        uint32_t sAf = sbase + (uint32_t)((i & 1) * 2 * STG) * 2u;
        uint32_t sBf = sAf + (uint32_t)STG * 2u;

#pragma unroll
        for (int ks = 0; ks < 4; ks++) {
            const int k0 = ks * 16;
            uint32_t fb[8][2];
#pragma unroll
            for (int jp = 0; jp < 4; jp++) {
                int nj = wn * 64 + jp * 16;
                uint32_t addr = sBf + (uint32_t)((nj + b_r) * SA + k0 + b_k) * 2u;
                uint32_t r4[4];
                ldsm4(r4, addr);
                fb[jp * 2][0]     = r4[0];
                fb[jp * 2][1]     = r4[1];
                fb[jp * 2 + 1][0] = r4[2];
                fb[jp * 2 + 1][1] = r4[3];
            }
#pragma unroll
            for (int ii = 0; ii < 2; ii++) {
                int m0 = wm * 32 + ii * 16;
                uint32_t addr = sAf + (uint32_t)((m0 + a_r) * SA + k0 + a_k) * 2u;
                uint32_t fa[4];
                ldsm4(fa, addr);
#pragma unroll
                for (int j = 0; j < 8; j++)
                    mma_f16(acc[ii][j], fa, fb[j]);
            }
        }
    }

    // ---- epilogue: store fp16 ----
    const int lq = lane >> 2;
    const int lr = lane & 3;
#pragma unroll
    for (int i = 0; i < 2; i++) {
        int r_lo = row0 + wm * 32 + i * 16 + lq;
        int r_hi = r_lo + 8;
#pragma unroll
        for (int j = 0; j < 8; j++) {
            int col = bn + wn * 64 + j * 8 + lr * 2;
            if (r_lo < M) {
                __half2 p = __floats2half2_rn(acc[i][j][0], acc[i][j][1]);
                *(uint32_t*)(C + (size_t)r_lo * DD + col) = *(uint32_t*)&p;
            }
            if (r_hi < M) {
                __half2 p = __floats2half2_rn(acc[i][j][2], acc[i][j][3]);
                *(uint32_t*)(C + (size_t)r_hi * DD + col) = *(uint32_t*)&p;
            }
        }
    }
}
#define GEMM_SMEM (2 * 2 * STG * 2)   // bytes = 73728

// ---------------------------------------------------------------------------
// Fused aggregate + norm + bias + ELU. Warp-level work stealing: each warp
// pulls node tickets from g_tick[tick_id] -> no block-retire imbalance.
template <bool OUT16>
__global__ __launch_bounds__(256)
void k_agg(const __half* __restrict__ xw16, const float* __restrict__ b,
           void* __restrict__ outp, int node_base, int node_cnt, int tick_id) {
    const int t = threadIdx.x & 31;
    const uint4* X = (const uint4*)xw16;

    for (;;) {
        int n;
        if (t == 0) n = atomicAdd(&g_tick[tick_id], 1);
        n = __shfl_sync(0xffffffffu, n, 0);
        if (n >= node_cnt) return;
        int node = node_base + n;

        float dn = g_dis[node];
        float acc[8];
        {
            uint4 v = __ldg(&X[(size_t)node * 32 + t]);
            const __half2* h2 = (const __half2*)&v;
#pragma unroll
            for (int q = 0; q < 4; q++) {
                float2 f = __half22float2(h2[q]);
                acc[2 * q]     = dn * f.x;
                acc[2 * q + 1] = dn * f.y;
            }
        }

        int beg = g_off[node];
        int end = g_off[node + 1];

        int e = beg;
        for (; e + 8 <= end; e += 8) {
            int2 ew[8];
#pragma unroll
            for (int q = 0; q < 8; q++) ew[q] = __ldg(&g_ew[e + q]);
            uint4 v[8];
#pragma unroll
            for (int q = 0; q < 8; q++)
                v[q] = __ldg(&X[(size_t)ew[q].x * 32 + t]);
#pragma unroll
            for (int q = 0; q < 8; q++) {
                float w = __int_as_float(ew[q].y);
                const __half2* a = (const __half2*)&v[q];
#pragma unroll
                for (int p = 0; p < 4; p++) {
                    float2 f = __half22float2(a[p]);
                    acc[2 * p]     += w * f.x;
                    acc[2 * p + 1] += w * f.y;
                }
            }
        }
        for (; e < end; e++) {
            int2 ew0 = __ldg(&g_ew[e]);
            float w0 = __int_as_float(ew0.y);
            uint4 v0 = __ldg(&X[(size_t)ew0.x * 32 + t]);
            const __half2* a0 = (const __half2*)&v0;
#pragma unroll
            for (int q = 0; q < 4; q++) {
                float2 f0 = __half22float2(a0[q]);
                acc[2 * q]     += w0 * f0.x;
                acc[2 * q + 1] += w0 * f0.y;
            }
        }

        float4 b0 = *(const float4*)(b + t * 8);
        float4 b1 = *(const float4*)(b + t * 8 + 4);
        float r[8];
        r[0] = dn * acc[0] + b0.x;  r[1] = dn * acc[1] + b0.y;
        r[2] = dn * acc[2] + b0.z;  r[3] = dn * acc[3] + b0.w;
        r[4] = dn * acc[4] + b1.x;  r[5] = dn * acc[5] + b1.y;
        r[6] = dn * acc[6] + b1.z;  r[7] = dn * acc[7] + b1.w;
#pragma unroll
        for (int q = 0; q < 8; q++)
            r[q] = r[q] > 0.f ? r[q] : expm1f(r[q]);

        if (OUT16) {
            __half2 p0 = __floats2half2_rn(r[0], r[1]);
            __half2 p1 = __floats2half2_rn(r[2], r[3]);
            __half2 p2 = __floats2half2_rn(r[4], r[5]);
            __half2 p3 = __floats2half2_rn(r[6], r[7]);
            uint4 v = make_uint4(*(uint32_t*)&p0, *(uint32_t*)&p1,
                                 *(uint32_t*)&p2, *(uint32_t*)&p3);
            *(uint4*)((__half*)outp + (size_t)node * DD + t * 8) = v;
        } else {
            float* O = (float*)outp + (size_t)node * DD + t * 8;
            __stcs((float4*)O,     make_float4(r[0], r[1], r[2], r[3]));
            __stcs((float4*)(O+4), make_float4(r[4], r[5], r[6], r[7]));
        }
    }
}

// ---------------------------------------------------------------------------
extern "C" void kernel_launch(void* const* d_in, const int* in_sizes, int n_in,
                              void* d_out, int out_size) {
    const float* x   = (const float*)d_in[0];
    const int*   ei  = (const int*)d_in[1];
    const float* W1  = (const float*)d_in[2];
    const float* b1  = (const float*)d_in[3];
    const float* W2  = (const float*)d_in[4];
    const float* b2  = (const float*)d_in[5];
    float*       out = (float*)d_out;

    __half *x16, *xw1, *xw2, *h16, *w1t, *w2t;
    cudaGetSymbolAddress((void**)&x16, g_x16);
    cudaGetSymbolAddress((void**)&xw1, g_xw1);
    cudaGetSymbolAddress((void**)&xw2, g_xw2);
    cudaGetSymbolAddress((void**)&h16, g_h16);
    cudaGetSymbolAddress((void**)&w1t, g_w1t);
    cudaGetSymbolAddress((void**)&w2t, g_w2t);

    cudaFuncSetAttribute(k_gemm_mma,
                         cudaFuncAttributeMaxDynamicSharedMemorySize, GEMM_SMEM);

    const int T = 256;
    int grid_n   = (N_NODES + T - 1) / T;
    int grid_e   = (E_EDGES + T - 1) / T;
    int grid_cvt = (N_NODES * DD / 8 + T - 1) / T;

    // 4-chunk layer-boundary interleave: 100000 = 3*25088 + 24736
    const int CH0 = 25088;                  // multiple of 128
    int chunk_beg[4] = {0, CH0, 2 * CH0, 3 * CH0};
    int chunk_cnt[4] = {CH0, CH0, CH0, N_NODES - 3 * CH0};

    dim3 gemm_all(DD / 128, (N_NODES + 127) / 128);
    const int AGG_GRID = 592;               // 148 SMs x 4 blocks, work-stealing

    cudaStream_t s2;
    cudaStreamCreate(&s2);
    cudaEvent_t evFork, evW, evJoin, evA[4], evG[4];
    cudaEventCreateWithFlags(&evFork, cudaEventDisableTiming);
    cudaEventCreateWithFlags(&evW,    cudaEventDisableTiming);
    cudaEventCreateWithFlags(&evJoin, cudaEventDisableTiming);
    for (int i = 0; i < 4; i++) {
        cudaEventCreateWithFlags(&evA[i], cudaEventDisableTiming);
        cudaEventCreateWithFlags(&evG[i], cudaEventDisableTiming);
    }

    // fork side stream
    cudaEventRecord(evFork, 0);
    cudaStreamWaitEvent(s2, evFork, 0);

    // main: weight conversions first, then CSR build
    k_wcvt<<<DD, DD>>>(W1, w1t);
    k_wcvt<<<DD, DD>>>(W2, w2t);
    cudaEventRecord(evW, 0);

    // s2: x conversion, then layer-1 GEMM -> xw1
    k_cvt_x<<<grid_cvt, T, 0, s2>>>(x);
    cudaStreamWaitEvent(s2, evW, 0);
    k_gemm_mma<<<gemm_all, T, GEMM_SMEM, s2>>>(x16, xw1, w1t, 0, N_NODES);
    cudaEventRecord(evJoin, s2);

    // main: edge decode + CSR build + normalization (overlaps with s2)
    k_detect  <<<1, 256>>>(ei);           // also zeroes g_tick[]
    k_zero_cnt<<<grid_n, T>>>();
    k_count   <<<grid_e, T>>>(ei);
    k_scan    <<<1, 1024>>>();
    k_fill    <<<grid_e, T>>>(ei);

    // join; layer-1 aggregation (reads xw1) in 4 chunks; GEMM-2 chunk
    // (reads h16 chunk, writes xw2 -- disjoint from xw1) trails on s2.
    cudaStreamWaitEvent(0, evJoin, 0);
    for (int i = 0; i < 4; i++) {
        k_agg<true><<<AGG_GRID, T>>>(xw1, b1, h16,
                                     chunk_beg[i], chunk_cnt[i], i);
        cudaEventRecord(evA[i], 0);
        cudaStreamWaitEvent(s2, evA[i], 0);
        dim3 g2(DD / 128, (chunk_cnt[i] + 127) / 128);
        k_gemm_mma<<<g2, T, GEMM_SMEM, s2>>>(h16, xw2, w2t,
                                             chunk_beg[i], N_NODES);
        cudaEventRecord(evG[i], s2);
    }

    // main: wait for all GEMM-2 chunks, then full layer-2 aggregation
    for (int i = 0; i < 4; i++) cudaStreamWaitEvent(0, evG[i], 0);
    k_agg<false><<<AGG_GRID, T>>>(xw2, b2, out, 0, N_NODES, 4);

    cudaStreamDestroy(s2);
    cudaEventDestroy(evFork);
    cudaEventDestroy(evW);
    cudaEventDestroy(evJoin);
    for (int i = 0; i < 4; i++) {
        cudaEventDestroy(evA[i]);
        cudaEventDestroy(evG[i]);
    }
}

// round 17
// speedup vs baseline: 1.2461x; 1.2068x over previous
#include <cuda_runtime.h>
#include <cuda_fp16.h>
#include <cstdint>
#include <math.h>

// Problem constants (fixed by the reference)
#define N_NODES 100000
#define E_EDGES 3200000
#define DD 256           // feature dim

// ---------------- scratch (static device allocations; no cudaMalloc) -------
__device__ int    g_is64;
__device__ int    g_cnt [N_NODES];
__device__ int    g_off [N_NODES + 1];
__device__ int    g_cur [N_NODES];
__device__ int2   g_ew  [E_EDGES];                // {src, bits(dis[src])} per CSR slot
__device__ float  g_dis [N_NODES];
__device__ __half g_x16 [N_NODES * DD];           // input features, fp16
__device__ __half g_xw1 [N_NODES * DD];           // layer-1 GEMM output
__device__ __half g_xw2 [N_NODES * DD];           // layer-2 GEMM output
__device__ __half g_h16 [N_NODES * DD];           // layer-1 activations, fp16
__device__ __half g_w1t [DD * DD];                // W1^T fp16 [n][k]
__device__ __half g_w2t [DD * DD];                // W2^T fp16 [n][k]

// ---------------------------------------------------------------------------
__global__ void k_detect(const int* __restrict__ ei32) {
    __shared__ int nz[256];
    int tid = threadIdx.x;
    int acc = 0;
    for (int i = tid; i < 2048; i += 256)
        acc += (ei32[2 * i + 1] != 0) ? 1 : 0;
    nz[tid] = acc;
    __syncthreads();
    for (int s = 128; s > 0; s >>= 1) {
        if (tid < s) nz[tid] += nz[tid + s];
        __syncthreads();
    }
    if (tid == 0) g_is64 = (nz[0] == 0) ? 1 : 0;
}

__global__ void k_zero_cnt() {
    int i = blockIdx.x * blockDim.x + threadIdx.x;
    if (i < N_NODES) g_cnt[i] = 0;
}

// histogram pass: decode dst on the fly
__global__ void k_count(const int* __restrict__ ei32) {
    int e = blockIdx.x * blockDim.x + threadIdx.x;
    if (e >= E_EDGES) return;
    int t = g_is64 ? ei32[2 * (E_EDGES + e)] : ei32[E_EDGES + e];
    atomicAdd(&g_cnt[t], 1);
}

__global__ __launch_bounds__(1024)
void k_scan() {
    __shared__ int sums[1024];
    const int tid = threadIdx.x;
    const int CH  = (N_NODES + 1023) / 1024;
    int beg = tid * CH;
    int end = beg + CH; if (end > N_NODES) end = N_NODES;
    if (beg > N_NODES) beg = N_NODES;

    int s = 0;
    for (int i = beg; i < end; i++) s += g_cnt[i];
    sums[tid] = s;
    __syncthreads();
    for (int off = 1; off < 1024; off <<= 1) {
        int v = (tid >= off) ? sums[tid - off] : 0;
        __syncthreads();
        sums[tid] += v;
        __syncthreads();
    }
    int run = (tid > 0) ? sums[tid - 1] : 0;
    for (int i = beg; i < end; i++) {
        int c = g_cnt[i];
        g_off[i] = run;
        g_cur[i] = run;
        g_dis[i] = rsqrtf((float)(c + 1));
        run += c;
    }
    if (tid == 0) g_off[N_NODES] = sums[1023];
}

// fill CSR slots with packed {src, dis[src]}; decode edges on the fly
__global__ void k_fill(const int* __restrict__ ei32) {
    int e = blockIdx.x * blockDim.x + threadIdx.x;
    if (e >= E_EDGES) return;
    int s, t;
    if (g_is64) {
        s = ei32[2 * e];
        t = ei32[2 * (E_EDGES + e)];
    } else {
        s = ei32[e];
        t = ei32[E_EDGES + e];
    }
    int p = atomicAdd(&g_cur[t], 1);
    g_ew[p] = make_int2(s, __float_as_int(g_dis[s]));
}

// ---------------------------------------------------------------------------
// x (fp32) -> fp16 copy
__global__ void k_cvt_x(const float* __restrict__ x) {
    int idx = blockIdx.x * blockDim.x + threadIdx.x;
    if (idx >= N_NODES * DD / 8) return;
    float4 a = *(const float4*)(x + idx * 8);
    float4 b = *(const float4*)(x + idx * 8 + 4);
    __half2 p0 = __floats2half2_rn(a.x, a.y);
    __half2 p1 = __floats2half2_rn(a.z, a.w);
    __half2 p2 = __floats2half2_rn(b.x, b.y);
    __half2 p3 = __floats2half2_rn(b.z, b.w);
    uint4 v = make_uint4(*(uint32_t*)&p0, *(uint32_t*)&p1,
                         *(uint32_t*)&p2, *(uint32_t*)&p3);
    *(uint4*)(g_x16 + idx * 8) = v;
}

// W^T -> fp16:  wt[n][k] = fp16(W[k][n])
__global__ void k_wcvt(const float* __restrict__ W, __half* __restrict__ wt) {
    int idx = blockIdx.x * blockDim.x + threadIdx.x;
    int n = idx >> 8, k = idx & 255;
    wt[n * DD + k] = __float2half_rn(W[k * DD + n]);
}

// ---------------------------------------------------------------------------
// mma.sync wrapper: m16n8k16 fp16 -> f32
__device__ __forceinline__ void mma_f16(float* c, const uint32_t* a, const uint32_t* b) {
    asm volatile(
        "mma.sync.aligned.m16n8k16.row.col.f32.f16.f16.f32 "
        "{%0,%1,%2,%3}, {%4,%5,%6,%7}, {%8,%9}, {%0,%1,%2,%3};"
        : "+f"(c[0]), "+f"(c[1]), "+f"(c[2]), "+f"(c[3])
        : "r"(a[0]), "r"(a[1]), "r"(a[2]), "r"(a[3]), "r"(b[0]), "r"(b[1]));
}

__device__ __forceinline__ void ldsm4(uint32_t* r, uint32_t saddr) {
    asm volatile("ldmatrix.sync.aligned.m8n8.x4.shared.b16 {%0,%1,%2,%3}, [%4];"
                 : "=r"(r[0]), "=r"(r[1]), "=r"(r[2]), "=r"(r[3]) : "r"(saddr));
}

__device__ __forceinline__ void cp16(uint32_t saddr, const void* g) {
    asm volatile("cp.async.cg.shared.global [%0], [%1], 16;"
                 :: "r"(saddr), "l"(g) : "memory");
}
#define CP_COMMIT() asm volatile("cp.async.commit_group;" ::: "memory")
#define CP_WAIT0()  asm volatile("cp.async.wait_group 0;" ::: "memory")

// fp16 GEMM via mma.sync + ldmatrix, cp.async double-buffered, BK=64.
#define SA 72
#define STG (128 * SA)               // halfs per array per stage
__global__ __launch_bounds__(256, 2)
void k_gemm_mma(const __half* __restrict__ A, __half* __restrict__ C,
                const __half* __restrict__ Wt, int row_base, int M) {
    extern __shared__ __half sm[];   // [2][2][STG]: Af, Bf per stage

    const int tid  = threadIdx.x;
    const int wid  = tid >> 5;
    const int lane = tid & 31;
    const int wm   = wid & 3;
    const int wn   = wid >> 2;
    const int row0 = row_base + blockIdx.y * 128;
    const int bn   = blockIdx.x * 128;

    float acc[2][8][4];
#pragma unroll
    for (int i = 0; i < 2; i++)
#pragma unroll
        for (int j = 0; j < 8; j++)
#pragma unroll
            for (int q = 0; q < 4; q++) acc[i][j][q] = 0.0f;

    uint32_t sbase = (uint32_t)__cvta_generic_to_shared(sm);

    const int a_r = lane & 15;
    const int a_k = (lane >> 4) << 3;
    const int b_r = ((lane >> 4) << 3) + (lane & 7);
    const int b_k = ((lane >> 3) & 1) << 3;

    auto stage = [&](int p, int kb) {
        uint32_t bA = sbase + (uint32_t)(p * 2 * STG) * 2u;
        uint32_t bB = bA + (uint32_t)STG * 2u;
#pragma unroll
        for (int it = 0; it < 4; it++) {
            int idx = it * 256 + tid;     // 1024 uint4
            int r   = idx >> 3;           // 0..127
            int u   = idx & 7;            // 16B unit (8 per row)
            int gr  = row0 + r; if (gr >= M) gr = M - 1;
            cp16(bA + (uint32_t)(r * SA + u * 8) * 2u,
                 A + (size_t)gr * DD + kb + u * 8);
            cp16(bB + (uint32_t)(r * SA + u * 8) * 2u,
                 Wt + (size_t)(bn + r) * DD + kb + u * 8);
        }
        CP_COMMIT();
    };

    stage(0, 0);

    const int NK = DD / 64;              // 4 k-blocks
    for (int i = 0; i < NK; i++) {
        CP_WAIT0();
        __syncthreads();
        if (i + 1 < NK) stage((i + 1) & 1, (i + 1) * 64);

        uint32_t sAf = sbase + (uint32_t)((i & 1) * 2 * STG) * 2u;
        uint32_t sBf = sAf + (uint32_t)STG * 2u;

#pragma unroll
        for (int ks = 0; ks < 4; ks++) {
            const int k0 = ks * 16;
            uint32_t fb[8][2];
#pragma unroll
            for (int jp = 0; jp < 4; jp++) {
                int nj = wn * 64 + jp * 16;
                uint32_t addr = sBf + (uint32_t)((nj + b_r) * SA + k0 + b_k) * 2u;
                uint32_t r4[4];
                ldsm4(r4, addr);
                fb[jp * 2][0]     = r4[0];
                fb[jp * 2][1]     = r4[1];
                fb[jp * 2 + 1][0] = r4[2];
                fb[jp * 2 + 1][1] = r4[3];
            }
#pragma unroll
            for (int ii = 0; ii < 2; ii++) {
                int m0 = wm * 32 + ii * 16;
                uint32_t addr = sAf + (uint32_t)((m0 + a_r) * SA + k0 + a_k) * 2u;
                uint32_t fa[4];
                ldsm4(fa, addr);
#pragma unroll
                for (int j = 0; j < 8; j++)
                    mma_f16(acc[ii][j], fa, fb[j]);
            }
        }
    }

    // ---- epilogue: store fp16 ----
    const int lq = lane >> 2;
    const int lr = lane & 3;
#pragma unroll
    for (int i = 0; i < 2; i++) {
        int r_lo = row0 + wm * 32 + i * 16 + lq;
        int r_hi = r_lo + 8;
#pragma unroll
        for (int j = 0; j < 8; j++) {
            int col = bn + wn * 64 + j * 8 + lr * 2;
            if (r_lo < M) {
                __half2 p = __floats2half2_rn(acc[i][j][0], acc[i][j][1]);
                *(uint32_t*)(C + (size_t)r_lo * DD + col) = *(uint32_t*)&p;
            }
            if (r_hi < M) {
                __half2 p = __floats2half2_rn(acc[i][j][2], acc[i][j][3]);
                *(uint32_t*)(C + (size_t)r_hi * DD + col) = *(uint32_t*)&p;
            }
        }
    }
}
#define GEMM_SMEM (2 * 2 * STG * 2)   // bytes = 73728

// ---------------------------------------------------------------------------
// Fused aggregate + norm + bias + ELU from fp16 features.
// 8 nodes per 256-thread block, 32 threads/node (1 warp), uint4 per thread.
// Inner loop: 16-edge register-batched gathers (all index loads, then all
// feature gathers, then FMAs) for deep MLP without smem.
template <bool OUT16>
__global__ __launch_bounds__(256)
void k_agg(const __half* __restrict__ xw16, const float* __restrict__ b,
           void* __restrict__ outp, int node_base, int node_cnt) {
    int node = node_base + blockIdx.x * 8 + (threadIdx.x >> 5);
    if (node >= node_base + node_cnt) return;
    int t = threadIdx.x & 31;

    const uint4* X = (const uint4*)xw16;

    float dn = g_dis[node];
    float acc[8];
    {
        uint4 v = __ldg(&X[(size_t)node * 32 + t]);
        const __half2* h2 = (const __half2*)&v;
#pragma unroll
        for (int q = 0; q < 4; q++) {
            float2 f = __half22float2(h2[q]);
            acc[2 * q]     = dn * f.x;
            acc[2 * q + 1] = dn * f.y;
        }
    }

    int beg = g_off[node];
    int end = g_off[node + 1];

    int e = beg;
    // 16-edge register-pipelined batches
    for (; e + 16 <= end; e += 16) {
        int2 ew[16];
#pragma unroll
        for (int q = 0; q < 16; q++) ew[q] = __ldg(&g_ew[e + q]);
        uint4 v[16];
#pragma unroll
        for (int q = 0; q < 16; q++)
            v[q] = __ldg(&X[(size_t)ew[q].x * 32 + t]);
#pragma unroll
        for (int q = 0; q < 16; q++) {
            float w = __int_as_float(ew[q].y);
            const __half2* a = (const __half2*)&v[q];
#pragma unroll
            for (int p = 0; p < 4; p++) {
                float2 f = __half22float2(a[p]);
                acc[2 * p]     += w * f.x;
                acc[2 * p + 1] += w * f.y;
            }
        }
    }
    // 8-edge batch
    for (; e + 8 <= end; e += 8) {
        int2 ew[8];
#pragma unroll
        for (int q = 0; q < 8; q++) ew[q] = __ldg(&g_ew[e + q]);
        uint4 v[8];
#pragma unroll
        for (int q = 0; q < 8; q++)
            v[q] = __ldg(&X[(size_t)ew[q].x * 32 + t]);
#pragma unroll
        for (int q = 0; q < 8; q++) {
            float w = __int_as_float(ew[q].y);
            const __half2* a = (const __half2*)&v[q];
#pragma unroll
            for (int p = 0; p < 4; p++) {
                float2 f = __half22float2(a[p]);
                acc[2 * p]     += w * f.x;
                acc[2 * p + 1] += w * f.y;
            }
        }
    }
    for (; e < end; e++) {
        int2 ew0 = __ldg(&g_ew[e]);
        float w0 = __int_as_float(ew0.y);
        uint4 v0 = __ldg(&X[(size_t)ew0.x * 32 + t]);
        const __half2* a0 = (const __half2*)&v0;
#pragma unroll
        for (int q = 0; q < 4; q++) {
            float2 f0 = __half22float2(a0[q]);
            acc[2 * q]     += w0 * f0.x;
            acc[2 * q + 1] += w0 * f0.y;
        }
    }

    float4 b0 = *(const float4*)(b + t * 8);
    float4 b1 = *(const float4*)(b + t * 8 + 4);
    float r[8];
    r[0] = dn * acc[0] + b0.x;  r[1] = dn * acc[1] + b0.y;
    r[2] = dn * acc[2] + b0.z;  r[3] = dn * acc[3] + b0.w;
    r[4] = dn * acc[4] + b1.x;  r[5] = dn * acc[5] + b1.y;
    r[6] = dn * acc[6] + b1.z;  r[7] = dn * acc[7] + b1.w;
#pragma unroll
    for (int q = 0; q < 8; q++)
        r[q] = r[q] > 0.f ? r[q] : expm1f(r[q]);

    if (OUT16) {
        __half2 p0 = __floats2half2_rn(r[0], r[1]);
        __half2 p1 = __floats2half2_rn(r[2], r[3]);
        __half2 p2 = __floats2half2_rn(r[4], r[5]);
        __half2 p3 = __floats2half2_rn(r[6], r[7]);
        uint4 v = make_uint4(*(uint32_t*)&p0, *(uint32_t*)&p1,
                             *(uint32_t*)&p2, *(uint32_t*)&p3);
        *(uint4*)((__half*)outp + (size_t)node * DD + t * 8) = v;
    } else {
        float* O = (float*)outp + (size_t)node * DD + t * 8;
        __stcs((float4*)O,     make_float4(r[0], r[1], r[2], r[3]));
        __stcs((float4*)(O+4), make_float4(r[4], r[5], r[6], r[7]));
    }
}

// ---------------------------------------------------------------------------
extern "C" void kernel_launch(void* const* d_in, const int* in_sizes, int n_in,
                              void* d_out, int out_size) {
    const float* x   = (const float*)d_in[0];
    const int*   ei  = (const int*)d_in[1];
    const float* W1  = (const float*)d_in[2];
    const float* b1  = (const float*)d_in[3];
    const float* W2  = (const float*)d_in[4];
    const float* b2  = (const float*)d_in[5];
    float*       out = (float*)d_out;

    __half *x16, *xw1, *xw2, *h16, *w1t, *w2t;
    cudaGetSymbolAddress((void**)&x16, g_x16);
    cudaGetSymbolAddress((void**)&xw1, g_xw1);
    cudaGetSymbolAddress((void**)&xw2, g_xw2);
    cudaGetSymbolAddress((void**)&h16, g_h16);
    cudaGetSymbolAddress((void**)&w1t, g_w1t);
    cudaGetSymbolAddress((void**)&w2t, g_w2t);

    cudaFuncSetAttribute(k_gemm_mma,
                         cudaFuncAttributeMaxDynamicSharedMemorySize, GEMM_SMEM);

    const int T = 256;
    int grid_n   = (N_NODES + T - 1) / T;
    int grid_e   = (E_EDGES + T - 1) / T;
    int grid_cvt = (N_NODES * DD / 8 + T - 1) / T;

    // 4-chunk layer-boundary interleave: 100000 = 3*25088 + 24736
    const int CH0 = 25088;                  // multiple of 128
    int chunk_beg[4] = {0, CH0, 2 * CH0, 3 * CH0};
    int chunk_cnt[4] = {CH0, CH0, CH0, N_NODES - 3 * CH0};

    dim3 gemm_all(DD / 128, (N_NODES + 127) / 128);
    int agg_all = (N_NODES + 7) / 8;

    cudaStream_t s2;
    cudaStreamCreate(&s2);
    cudaEvent_t evFork, evW, evJoin, evA[4], evG[4];
    cudaEventCreateWithFlags(&evFork, cudaEventDisableTiming);
    cudaEventCreateWithFlags(&evW,    cudaEventDisableTiming);
    cudaEventCreateWithFlags(&evJoin, cudaEventDisableTiming);
    for (int i = 0; i < 4; i++) {
        cudaEventCreateWithFlags(&evA[i], cudaEventDisableTiming);
        cudaEventCreateWithFlags(&evG[i], cudaEventDisableTiming);
    }

    // fork side stream
    cudaEventRecord(evFork, 0);
    cudaStreamWaitEvent(s2, evFork, 0);

    // main: weight conversions first, then CSR build
    k_wcvt<<<DD, DD>>>(W1, w1t);
    k_wcvt<<<DD, DD>>>(W2, w2t);
    cudaEventRecord(evW, 0);

    // s2: x conversion, then layer-1 GEMM -> xw1
    k_cvt_x<<<grid_cvt, T, 0, s2>>>(x);
    cudaStreamWaitEvent(s2, evW, 0);
    k_gemm_mma<<<gemm_all, T, GEMM_SMEM, s2>>>(x16, xw1, w1t, 0, N_NODES);
    cudaEventRecord(evJoin, s2);

    // main: edge decode + CSR build + normalization (overlaps with s2)
    k_detect  <<<1, 256>>>(ei);
    k_zero_cnt<<<grid_n, T>>>();
    k_count   <<<grid_e, T>>>(ei);
    k_scan    <<<1, 1024>>>();
    k_fill    <<<grid_e, T>>>(ei);

    // join; layer-1 aggregation (reads xw1) in 4 chunks; GEMM-2 chunk
    // (reads h16 chunk, writes xw2 -- disjoint from xw1) trails on s2.
    cudaStreamWaitEvent(0, evJoin, 0);
    for (int i = 0; i < 4; i++) {
        k_agg<true><<<(chunk_cnt[i] + 7) / 8, T>>>(xw1, b1, h16,
                                                   chunk_beg[i], chunk_cnt[i]);
        cudaEventRecord(evA[i], 0);
        cudaStreamWaitEvent(s2, evA[i], 0);
        dim3 g2(DD / 128, (chunk_cnt[i] + 127) / 128);
        k_gemm_mma<<<g2, T, GEMM_SMEM, s2>>>(h16, xw2, w2t,
                                             chunk_beg[i], N_NODES);
        cudaEventRecord(evG[i], s2);
    }

    // main: wait for all GEMM-2 chunks, then full layer-2 aggregation
    for (int i = 0; i < 4; i++) cudaStreamWaitEvent(0, evG[i], 0);
    k_agg<false><<<agg_all, T>>>(xw2, b2, out, 0, N_NODES);

    cudaStreamDestroy(s2);
    cudaEventDestroy(evFork);
    cudaEventDestroy(evW);
    cudaEventDestroy(evJoin);
    for (int i = 0; i < 4; i++) {
        cudaEventDestroy(evA[i]);
        cudaEventDestroy(evG[i]);
    }
}